// round 10
// baseline (speedup 1.0000x reference)
#include <cuda_runtime.h>
#include <cstdint>

// ConstituencyMFVI: B=8, N=192, 3 mean-field iterations.
// q[b,i,j] = s_span[b,i,j] + (j>i) * sum_{k != i, k != j} sigmoid(q[b,i,k]) * s_pair[b,i,j,k]
// out = sigmoid(q).
//
// R10: register-resident tiles, zero SMEM data path.
// 148 persistent CTAs (1/SM) x 384 threads. Thread (h, jj) owns cols
// [96h, 96h+96) of row jj: 24 x LDG.128 straight into registers (no SMEM
// staging -> no bank conflicts, no crossbar tax). Exclusions k==i / k==j are
// SUBTRACTED at combine time (sig[i]*P[j,i] + sig[j]*P[j,j], 2 scalar LDGs)
// instead of zeroing registers. SMEM holds only sig[192] + part[192].
// DRAM duty during compute comes from prefetch.global.L2 of tile n+2's
// contiguous row range (R*768 bytes), so demand LDGs hit L2.
// Rows j<=i never read (mask analytic): 113MB total HBM.

namespace {
constexpr int NN      = 192;
constexpr int NSM     = 148;
constexpr int THREADS = 384;
constexpr int CH      = 24;      // float4 chunks per half row
constexpr int NTILES  = 1536;
}

__device__ __forceinline__ float sigmoidf(float x) {
    return 1.0f / (1.0f + __expf(-x));
}

__global__ __launch_bounds__(THREADS, 1)
void mfvi_kernel(const float* __restrict__ s_span,
                 const float* __restrict__ s_pair,
                 float* __restrict__ out)
{
    __shared__ float sig[NN];
    __shared__ float part[NN];

    const int s = blockIdx.x;
    const int t = threadIdx.x;
    const bool hi = t >= NN;           // high-half threads
    const int jj  = hi ? t - NN : t;   // my row
    const int m   = (NTILES - s + NSM - 1) / NSM;   // 10 or 11 tiles

    // prefetch the whole active-row range of tile n into L2 (contiguous bytes)
    auto prefetch_tile = [&](int n) {
        if (n >= m) return;
        int g = s + n * NSM;
        int i = g >> 3;
        int R = NN - 1 - i;
        if (R <= 0) return;
        const char* p0 = (const char*)(s_pair
                         + (size_t)((g & 7) * NN + i) * (NN * NN)
                         + (size_t)(i + 1) * NN);
        int nl = R * 6;                // 128B lines (768 B per row)
        for (int x = t; x < nl; x += THREADS)
            asm volatile("prefetch.global.L2 [%0];" :: "l"(p0 + (size_t)x * 128));
    };

    prefetch_tile(0);
    prefetch_tile(1);

    #pragma unroll 1
    for (int n = 0; n < m; n++) {
        const int g  = s + n * NSM;
        const int i  = g >> 3;
        const int tz = (g & 7) * NN + i;
        const bool act = jj > i;

        const float* gP = s_pair + (size_t)tz * (NN * NN);

        // ---- my half row -> registers (24 x LDG.128, front-batched) ----
        float4 r[CH];
        if (act) {
            const float4* src = reinterpret_cast<const float4*>(
                gP + (size_t)jj * NN + (hi ? 96 : 0));
            #pragma unroll
            for (int c = 0; c < CH; c++) r[c] = __ldg(src + c);
        }

        // ---- per-row scalars (low-half threads own the row's q) ----
        float sv = 0.0f, ex_i = 0.0f, ex_j = 0.0f;
        if (!hi) {
            float sval = s_span[(size_t)tz * NN + t];
            if (t <= i) {                        // constant rows
                float v = sigmoidf(sval);
                sig[t] = v;
                out[(size_t)tz * NN + t] = v;
            } else {
                sv = sval;
                sig[t] = sigmoidf(sval);         // sigma^0
                ex_i = __ldg(gP + (size_t)t * NN + i);   // P[j, i]
                ex_j = __ldg(gP + (size_t)t * NN + t);   // P[j, j]
            }
        }

        prefetch_tile(n + 2);                    // keep DRAM streaming ahead

        __syncthreads();                         // sigma^0 visible

        #pragma unroll 1
        for (int it = 0; it < 3; it++) {
            float p = 0.0f;
            if (act) {
                const float4* sg4 = reinterpret_cast<const float4*>(sig) + (hi ? CH : 0);
                float ax = 0.f, ay = 0.f, az = 0.f, aw = 0.f;
                #pragma unroll
                for (int c = 0; c < CH; c++) {
                    float4 sgv = sg4[c];
                    ax = fmaf(r[c].x, sgv.x, ax);
                    ay = fmaf(r[c].y, sgv.y, ay);
                    az = fmaf(r[c].z, sgv.z, az);
                    aw = fmaf(r[c].w, sgv.w, aw);
                }
                p = (ax + ay) + (az + aw);
                if (hi) part[jj] = p;
            }
            __syncthreads();                     // partials published; sig reads done
            if (!hi && act) {
                // full dot minus excluded k==i and k==j terms
                float q = sv + p + part[t] - sig[i] * ex_i - sig[t] * ex_j;
                float v = sigmoidf(q);
                if (it < 2) sig[t] = v;
                else        out[(size_t)tz * NN + t] = v;
            }
            __syncthreads();                     // sig stable for next dot / next tile
        }
    }
}

extern "C" void kernel_launch(void* const* d_in, const int* in_sizes, int n_in,
                              void* d_out, int out_size)
{
    const float* s_span = (const float*)d_in[0];
    const float* s_pair = (const float*)d_in[1];
    float* out = (float*)d_out;

    mfvi_kernel<<<NSM, THREADS>>>(s_span, s_pair, out);
}

// round 11
// speedup vs baseline: 2.0974x; 2.0974x over previous
#include <cuda_runtime.h>
#include <cstdint>

// ConstituencyMFVI: B=8, N=192, 3 mean-field iterations.
// q[b,i,j] = s_span[b,i,j] + (j>i) * sum_{k != i, k != j} sigmoid(q[b,i,k]) * s_pair[b,i,j,k]
// out = sigmoid(q).
//
// R11: persistent CTAs + cp.async staging + REGISTER-resident rows.
// 148 persistent CTAs (1/SM) x 384 threads. Thread (h, jj) owns cols
// [96h, 96h+96) of row jj. Tiles stream through three rotating 192x100 SMEM
// half-buffers via coalesced cp.async; on arrival each thread copies its 24
// float4 to registers ONCE and the buffer is freed immediately -> during the
// 3-iteration compute all three buffers are refilling (H(n+1), L(n+2) in
// flight, ~110KB/SM) so the DRAM stream never stops. Compute is pure
// register FMA + broadcast sig reads (no per-iteration tile SMEM traffic).
// Exclusions k==i / k==j are subtracted at combine time using two scalars
// read from the staged buffers. Rows j<=i never loaded: 113MB total HBM.

namespace {
constexpr int NN      = 192;
constexpr int HALF    = 96;
constexpr int CH      = 24;          // float4 chunks per half row
constexpr int PADH    = 100;         // half-row stride (100%32==4 -> conflict-free LDS.128)
constexpr int THREADS = 384;
constexpr int NSM     = 148;
constexpr int NTILES  = 1536;
constexpr int HB      = NN * PADH;   // floats per half buffer
constexpr int SMEM_BYTES = (3 * HB + 2 * NN) * 4;   // 231,936
}

__device__ __forceinline__ float sigmoidf(float x) {
    return 1.0f / (1.0f + __expf(-x));
}

__global__ __launch_bounds__(THREADS, 1)
void mfvi_kernel(const float* __restrict__ s_span,
                 const float* __restrict__ s_pair,
                 float* __restrict__ out)
{
    extern __shared__ float smf[];
    float* bufs = smf;                 // 3 x [192][PADH]
    float* sig  = smf + 3 * HB;        // [192]
    float* part = sig + NN;            // [192]

    const int s  = blockIdx.x;
    const int t  = threadIdx.x;
    const bool h0 = t < NN;            // low-half threads (own the row's q)
    const int jj = h0 ? t : t - NN;    // my row
    const int m  = (NTILES - s + NSM - 1) / NSM;   // 10 or 11 tiles

    const int rr0 = t / CH;            // 0..15
    const int cc0 = t % CH;

    // issue one half (xoff 0 or 96) of tile n into buffer `bi`; ALWAYS commits
    // exactly one group (empty if n out of range or no active rows).
    auto issue_half = [&](int bi, int n, int xoff) {
        if (n < m) {
            int g = s + n * NSM;
            int i = g >> 3;
            int R = NN - 1 - i;
            const float* gP = s_pair + (size_t)((g & 7) * NN + i) * (NN * NN);
            uint32_t sb = (uint32_t)__cvta_generic_to_shared(bufs + bi * HB);
            for (int rr = rr0; rr < R; rr += 16) {
                int row = i + 1 + rr;
                uint32_t dst = sb + (uint32_t)(row * PADH + cc0 * 4) * 4u;
                const float* src = gP + (size_t)row * NN + xoff + cc0 * 4;
                asm volatile("cp.async.cg.shared.global [%0], [%1], 16;\n"
                             :: "r"(dst), "l"(src));
            }
        }
        asm volatile("cp.async.commit_group;\n");
    };

    // ---- prologue: L0 -> buf0, H0 -> buf1, L1 -> buf2 ----
    issue_half(0, 0, 0);
    issue_half(1, 0, HALF);
    issue_half(2, 1, 0);

    float4 r[CH];

    #pragma unroll 1
    for (int n = 0; n < m; n++) {
        const int g  = s + n * NSM;
        const int i  = g >> 3;
        const int tz = (g & 7) * NN + i;
        const int bl = (2 * n) % 3;        // low-half buffer of tile n
        const int bh = (2 * n + 1) % 3;    // high-half buffer
        const bool act = jj > i;

        // ---- both halves of tile n resident (only L(n+1) may be pending) ----
        asm volatile("cp.async.wait_group 1;\n");
        __syncthreads();

        // copy my half row to registers; low threads also grab per-row scalars
        float sv = 0.0f, ex_i = 0.0f, ex_j = 0.0f;
        if (act) {
            const float4* r4 = reinterpret_cast<const float4*>(
                bufs + (h0 ? bl : bh) * HB + jj * PADH);
            #pragma unroll
            for (int c = 0; c < CH; c++) r[c] = r4[c];
        }
        if (h0) {
            float sval = s_span[(size_t)tz * NN + t];
            if (t <= i) {                        // constant rows: sigma fixed
                float v = sigmoidf(sval);
                sig[t] = v;
                out[(size_t)tz * NN + t] = v;
            } else {
                sv = sval;
                sig[t] = sigmoidf(sval);         // sigma^0
                const float* Lrow = bufs + bl * HB + t * PADH;
                const float* Hrow = bufs + bh * HB + t * PADH;
                ex_i = (i < HALF) ? Lrow[i] : Hrow[i - HALF];   // P[j, i]
                ex_j = (t < HALF) ? Lrow[t] : Hrow[t - HALF];   // P[j, j]
            }
        }
        __syncthreads();                         // copies + sig^0 done -> buffers free

        // refill both freed buffers while we compute
        issue_half(bl, n + 1, HALF);             // H(n+1) -> (2n+3)%3 == bl
        issue_half(bh, n + 2, 0);                // L(n+2) -> (2n+4)%3 == bh

        const float4* sg4 = reinterpret_cast<const float4*>(sig) + (h0 ? 0 : CH);

        #pragma unroll 1
        for (int it = 0; it < 3; it++) {
            float p = 0.0f;
            if (act) {
                float ax = 0.f, ay = 0.f, az = 0.f, aw = 0.f;
                #pragma unroll
                for (int c = 0; c < CH; c++) {
                    float4 sgv = sg4[c];
                    ax = fmaf(r[c].x, sgv.x, ax);
                    ay = fmaf(r[c].y, sgv.y, ay);
                    az = fmaf(r[c].z, sgv.z, az);
                    aw = fmaf(r[c].w, sgv.w, aw);
                }
                p = (ax + ay) + (az + aw);
                if (!h0) part[jj] = p;
            }
            __syncthreads();                     // partials published; sig reads done
            if (h0 && act) {
                float q = sv + p + part[t] - sig[i] * ex_i - sig[t] * ex_j;
                float v = sigmoidf(q);
                if (it < 2) sig[t] = v;
                else        out[(size_t)tz * NN + t] = v;
            }
            __syncthreads();                     // sig stable for next pass
        }
    }
}

extern "C" void kernel_launch(void* const* d_in, const int* in_sizes, int n_in,
                              void* d_out, int out_size)
{
    const float* s_span = (const float*)d_in[0];
    const float* s_pair = (const float*)d_in[1];
    float* out = (float*)d_out;

    cudaFuncSetAttribute(mfvi_kernel,
                         cudaFuncAttributeMaxDynamicSharedMemorySize, SMEM_BYTES);

    mfvi_kernel<<<NSM, THREADS, SMEM_BYTES>>>(s_span, s_pair, out);
}